// round 1
// baseline (speedup 1.0000x reference)
#include <cuda_runtime.h>

// Transformer block, fused, fp32, f32x2-packed FMA path.
// B=4096 batches, T=64 tokens, C=64 embd, H=8 heads, D=8 head_size, FF=256.
// One CTA per batch element, 256 threads (8 warps).

#define Tn 64
#define Cn 64
#define Hn 8
#define SA 68          // padded row stride for activation buffers (floats)
#define EPSV 1e-5f
#define SCALEV 0.125f  // 64^-0.5

typedef unsigned long long ull;

__device__ __forceinline__ ull pack2(float a, float b) {
    ull r;
    asm("mov.b64 %0, {%1, %2};" : "=l"(r) : "f"(a), "f"(b));
    return r;
}
__device__ __forceinline__ void unpack2(ull v, float& a, float& b) {
    asm("mov.b64 {%0, %1}, %2;" : "=f"(a), "=f"(b) : "l"(v));
}
__device__ __forceinline__ ull fma2(ull a, ull b, ull c) {
    ull d;
    asm("fma.rn.f32x2 %0, %1, %2, %3;" : "=l"(d) : "l"(a), "l"(b), "l"(c));
    return d;
}
__device__ __forceinline__ ull mul2(ull a, ull b) {
    ull d;
    asm("mul.rn.f32x2 %0, %1, %2;" : "=l"(d) : "l"(a), "l"(b));
    return d;
}

// C[4x4] += A[4x64] * W[64x4]  (A stride SA, W stride 64)
// acc[i][0] = cols (c0, c0+1), acc[i][1] = cols (c0+2, c0+3), rows r0..r0+3
__device__ __forceinline__ void gemm_tile(const float* __restrict__ A,
                                          const float* __restrict__ W,
                                          ull acc[4][2], int r0, int c0) {
    #pragma unroll 4
    for (int k0 = 0; k0 < 64; k0 += 4) {
        float4 a0 = *(const float4*)&A[(r0 + 0) * SA + k0];
        float4 a1 = *(const float4*)&A[(r0 + 1) * SA + k0];
        float4 a2 = *(const float4*)&A[(r0 + 2) * SA + k0];
        float4 a3 = *(const float4*)&A[(r0 + 3) * SA + k0];
        #pragma unroll
        for (int j = 0; j < 4; j++) {
            float4 w = *(const float4*)&W[(k0 + j) * 64 + c0];
            ull wlo = pack2(w.x, w.y);
            ull whi = pack2(w.z, w.w);
            float e0 = (j == 0) ? a0.x : (j == 1) ? a0.y : (j == 2) ? a0.z : a0.w;
            float e1 = (j == 0) ? a1.x : (j == 1) ? a1.y : (j == 2) ? a1.z : a1.w;
            float e2 = (j == 0) ? a2.x : (j == 1) ? a2.y : (j == 2) ? a2.z : a2.w;
            float e3 = (j == 0) ? a3.x : (j == 1) ? a3.y : (j == 2) ? a3.z : a3.w;
            ull p0 = pack2(e0, e0), p1 = pack2(e1, e1);
            ull p2 = pack2(e2, e2), p3 = pack2(e3, e3);
            acc[0][0] = fma2(p0, wlo, acc[0][0]);
            acc[0][1] = fma2(p0, whi, acc[0][1]);
            acc[1][0] = fma2(p1, wlo, acc[1][0]);
            acc[1][1] = fma2(p1, whi, acc[1][1]);
            acc[2][0] = fma2(p2, wlo, acc[2][0]);
            acc[2][1] = fma2(p2, whi, acc[2][1]);
            acc[3][0] = fma2(p3, wlo, acc[3][0]);
            acc[3][1] = fma2(p3, whi, acc[3][1]);
        }
    }
}

__global__ void __launch_bounds__(256, 1)
block_kernel(const float* __restrict__ x,
             const float* __restrict__ Wq, const float* __restrict__ Wk,
             const float* __restrict__ Wv, const float* __restrict__ Wo,
             const float* __restrict__ bo,
             const float* __restrict__ W1, const float* __restrict__ b1,
             const float* __restrict__ W2, const float* __restrict__ b2,
             const float* __restrict__ g1, const float* __restrict__ be1,
             const float* __restrict__ g2, const float* __restrict__ be2,
             float* __restrict__ out) {
    extern __shared__ float sm[];
    float* xs = sm;                 // 64*SA : residual / x1
    float* hs = xs + 64 * SA;       // 64*SA : LN out / attn out
    float* qs = hs + 64 * SA;       // 64*SA
    float* ks = qs + 64 * SA;       // 64*SA
    float* vs = ks + 64 * SA;       // 64*SA
    float* wb = vs + 64 * SA;       // 4*4096 : Wq,Wk,Wv,Wo -> later W1c,W2c
    float* fs = qs;                 // alias: relu activations (FF phase)

    const int tid = threadIdx.x;
    const int b = blockIdx.x;
    const float* xg = x + (size_t)b * (Tn * Cn);
    float* og = out + (size_t)b * (Tn * Cn);

    // ---- Phase 0: stage attention weights, load x, LN1 -> hs ----
    {
        const float* srcs[4] = {Wq, Wk, Wv, Wo};
        #pragma unroll
        for (int m = 0; m < 4; m++) {
            const float4* s4 = (const float4*)srcs[m];
            float4* d4 = (float4*)(wb + m * 4096);
            #pragma unroll
            for (int p = tid; p < 1024; p += 256) d4[p] = s4[p];
        }
    }
    {
        const int t = tid >> 2, g = tid & 3;
        float4 xv[4];
        float s = 0.f, ss = 0.f;
        #pragma unroll
        for (int i = 0; i < 4; i++) {
            xv[i] = *(const float4*)&xg[t * 64 + g * 16 + i * 4];
            s += xv[i].x + xv[i].y + xv[i].z + xv[i].w;
            ss += xv[i].x * xv[i].x + xv[i].y * xv[i].y +
                  xv[i].z * xv[i].z + xv[i].w * xv[i].w;
        }
        s  += __shfl_xor_sync(0xffffffffu, s, 1);
        s  += __shfl_xor_sync(0xffffffffu, s, 2);
        ss += __shfl_xor_sync(0xffffffffu, ss, 1);
        ss += __shfl_xor_sync(0xffffffffu, ss, 2);
        float mu = s * (1.0f / 64.0f);
        float var = ss * (1.0f / 64.0f) - mu * mu;
        float rstd = rsqrtf(var + EPSV);
        #pragma unroll
        for (int i = 0; i < 4; i++) {
            int c = g * 16 + i * 4;
            float4 gv = *(const float4*)&g1[c];
            float4 bv = *(const float4*)&be1[c];
            float4 hv;
            hv.x = (xv[i].x - mu) * rstd * gv.x + bv.x;
            hv.y = (xv[i].y - mu) * rstd * gv.y + bv.y;
            hv.z = (xv[i].z - mu) * rstd * gv.z + bv.z;
            hv.w = (xv[i].w - mu) * rstd * gv.w + bv.w;
            *(float4*)&xs[t * SA + c] = xv[i];
            *(float4*)&hs[t * SA + c] = hv;
        }
    }
    __syncthreads();

    const int rg = tid >> 4, cg = tid & 15;
    const int r0 = rg * 4, c0 = cg * 4;

    // ---- Phase 1: q,k,v = hs @ Wq/k/v   (q pre-scaled by 0.125) ----
    {
        float* outs[3] = {qs, ks, vs};
        #pragma unroll
        for (int m = 0; m < 3; m++) {
            ull acc[4][2] = {{0, 0}, {0, 0}, {0, 0}, {0, 0}};
            gemm_tile(hs, wb + m * 4096, acc, r0, c0);
            const float scale = (m == 0) ? SCALEV : 1.0f;
            #pragma unroll
            for (int i = 0; i < 4; i++) {
                float v0, v1, v2, v3;
                unpack2(acc[i][0], v0, v1);
                unpack2(acc[i][1], v2, v3);
                float4 o = {v0 * scale, v1 * scale, v2 * scale, v3 * scale};
                *(float4*)&outs[m][(r0 + i) * SA + c0] = o;
            }
        }
    }
    __syncthreads();

    // ---- Phase 2: causal attention (warp = head, lane rows {l, 63-l}) ----
    {
        const int wrp = tid >> 5, l = tid & 31;
        const int hoff = wrp * 8;
        #pragma unroll
        for (int rr = 0; rr < 2; rr++) {
            const int t = (rr == 0) ? l : (63 - l);
            float4 q0 = *(const float4*)&qs[t * SA + hoff];
            float4 q1 = *(const float4*)&qs[t * SA + hoff + 4];
            ull qp0 = pack2(q0.x, q0.y), qp1 = pack2(q0.z, q0.w);
            ull qp2 = pack2(q1.x, q1.y), qp3 = pack2(q1.z, q1.w);
            ull o0 = 0, o1 = 0, o2 = 0, o3 = 0;
            float sum = 0.f;
            for (int s = 0; s <= t; s++) {
                float4 k0v = *(const float4*)&ks[s * SA + hoff];
                float4 k1v = *(const float4*)&ks[s * SA + hoff + 4];
                ull sc = fma2(qp0, pack2(k0v.x, k0v.y), 0ull);
                sc = fma2(qp1, pack2(k0v.z, k0v.w), sc);
                sc = fma2(qp2, pack2(k1v.x, k1v.y), sc);
                sc = fma2(qp3, pack2(k1v.z, k1v.w), sc);
                float sa, sb;
                unpack2(sc, sa, sb);
                float e = __expf(sa + sb);   // scores tiny: max-sub not needed
                sum += e;
                ull ep = pack2(e, e);
                float4 v0v = *(const float4*)&vs[s * SA + hoff];
                float4 v1v = *(const float4*)&vs[s * SA + hoff + 4];
                o0 = fma2(ep, pack2(v0v.x, v0v.y), o0);
                o1 = fma2(ep, pack2(v0v.z, v0v.w), o1);
                o2 = fma2(ep, pack2(v1v.x, v1v.y), o2);
                o3 = fma2(ep, pack2(v1v.z, v1v.w), o3);
            }
            float inv = 1.0f / sum;
            ull ip = pack2(inv, inv);
            *(ull*)&hs[t * SA + hoff + 0] = mul2(o0, ip);
            *(ull*)&hs[t * SA + hoff + 2] = mul2(o1, ip);
            *(ull*)&hs[t * SA + hoff + 4] = mul2(o2, ip);
            *(ull*)&hs[t * SA + hoff + 6] = mul2(o3, ip);
        }
    }
    __syncthreads();

    // ---- Phase 3: x1 = x + attn @ Wo + bo   (in-place into xs) ----
    {
        ull acc[4][2] = {{0, 0}, {0, 0}, {0, 0}, {0, 0}};
        gemm_tile(hs, wb + 3 * 4096, acc, r0, c0);
        float4 bov = *(const float4*)&bo[c0];
        #pragma unroll
        for (int i = 0; i < 4; i++) {
            float v0, v1, v2, v3;
            unpack2(acc[i][0], v0, v1);
            unpack2(acc[i][1], v2, v3);
            float4 xv = *(const float4*)&xs[(r0 + i) * SA + c0];
            xv.x += v0 + bov.x;
            xv.y += v1 + bov.y;
            xv.z += v2 + bov.z;
            xv.w += v3 + bov.w;
            *(float4*)&xs[(r0 + i) * SA + c0] = xv;
        }
    }
    __syncthreads();

    // ---- Phase 4: LN2(xs) -> hs ----
    {
        const int t = tid >> 2, g = tid & 3;
        float4 xv[4];
        float s = 0.f, ss = 0.f;
        #pragma unroll
        for (int i = 0; i < 4; i++) {
            xv[i] = *(const float4*)&xs[t * SA + g * 16 + i * 4];
            s += xv[i].x + xv[i].y + xv[i].z + xv[i].w;
            ss += xv[i].x * xv[i].x + xv[i].y * xv[i].y +
                  xv[i].z * xv[i].z + xv[i].w * xv[i].w;
        }
        s  += __shfl_xor_sync(0xffffffffu, s, 1);
        s  += __shfl_xor_sync(0xffffffffu, s, 2);
        ss += __shfl_xor_sync(0xffffffffu, ss, 1);
        ss += __shfl_xor_sync(0xffffffffu, ss, 2);
        float mu = s * (1.0f / 64.0f);
        float var = ss * (1.0f / 64.0f) - mu * mu;
        float rstd = rsqrtf(var + EPSV);
        #pragma unroll
        for (int i = 0; i < 4; i++) {
            int c = g * 16 + i * 4;
            float4 gv = *(const float4*)&g2[c];
            float4 bv = *(const float4*)&be2[c];
            float4 hv;
            hv.x = (xv[i].x - mu) * rstd * gv.x + bv.x;
            hv.y = (xv[i].y - mu) * rstd * gv.y + bv.y;
            hv.z = (xv[i].z - mu) * rstd * gv.z + bv.z;
            hv.w = (xv[i].w - mu) * rstd * gv.w + bv.w;
            *(float4*)&hs[t * SA + c] = hv;
        }
    }
    __syncthreads();

    // ---- Phase 5: FFN in 4 hidden chunks of 64; FF2 acc in registers ----
    ull accf[4][2] = {{0, 0}, {0, 0}, {0, 0}, {0, 0}};
    for (int cch = 0; cch < 4; cch++) {
        // stage W1 chunk (cols cch*64..) and W2 chunk (rows cch*64..)
        #pragma unroll
        for (int p = tid; p < 1024; p += 256) {
            int k = p >> 4, j4 = p & 15;
            *(float4*)&wb[k * 64 + j4 * 4] =
                *(const float4*)&W1[k * 256 + cch * 64 + j4 * 4];
        }
        {
            const float4* s4 = (const float4*)(W2 + cch * 4096);
            float4* d4 = (float4*)(wb + 4096);
            #pragma unroll
            for (int p = tid; p < 1024; p += 256) d4[p] = s4[p];
        }
        __syncthreads();

        // a1 = relu(hs @ W1c + b1c) -> fs
        {
            ull a1[4][2] = {{0, 0}, {0, 0}, {0, 0}, {0, 0}};
            gemm_tile(hs, wb, a1, r0, c0);
            float4 b1v = *(const float4*)&b1[cch * 64 + c0];
            #pragma unroll
            for (int i = 0; i < 4; i++) {
                float v0, v1, v2, v3;
                unpack2(a1[i][0], v0, v1);
                unpack2(a1[i][1], v2, v3);
                float4 o;
                o.x = fmaxf(v0 + b1v.x, 0.f);
                o.y = fmaxf(v1 + b1v.y, 0.f);
                o.z = fmaxf(v2 + b1v.z, 0.f);
                o.w = fmaxf(v3 + b1v.w, 0.f);
                *(float4*)&fs[(r0 + i) * SA + c0] = o;
            }
        }
        __syncthreads();

        // accf += fs @ W2c
        gemm_tile(fs, wb + 4096, accf, r0, c0);
        __syncthreads();  // protect wb before next chunk's staging
    }

    // ---- Phase 6: out = x1 + ff + b2 ----
    {
        float4 b2v = *(const float4*)&b2[c0];
        #pragma unroll
        for (int i = 0; i < 4; i++) {
            float v0, v1, v2, v3;
            unpack2(accf[i][0], v0, v1);
            unpack2(accf[i][1], v2, v3);
            float4 xv = *(const float4*)&xs[(r0 + i) * SA + c0];
            float4 o;
            o.x = xv.x + v0 + b2v.x;
            o.y = xv.y + v1 + b2v.y;
            o.z = xv.z + v2 + b2v.z;
            o.w = xv.w + v3 + b2v.w;
            *(float4*)&og[(r0 + i) * 64 + c0] = o;
        }
    }
}

extern "C" void kernel_launch(void* const* d_in, const int* in_sizes, int n_in,
                              void* d_out, int out_size) {
    (void)in_sizes; (void)n_in; (void)out_size;
    const float* x   = (const float*)d_in[0];
    const float* Wq  = (const float*)d_in[1];
    const float* Wk  = (const float*)d_in[2];
    const float* Wv  = (const float*)d_in[3];
    const float* Wo  = (const float*)d_in[4];
    const float* bo  = (const float*)d_in[5];
    const float* W1  = (const float*)d_in[6];
    const float* b1  = (const float*)d_in[7];
    const float* W2  = (const float*)d_in[8];
    const float* b2  = (const float*)d_in[9];
    const float* g1  = (const float*)d_in[10];
    const float* be1 = (const float*)d_in[11];
    const float* g2  = (const float*)d_in[12];
    const float* be2 = (const float*)d_in[13];
    float* out = (float*)d_out;

    const size_t smem = (size_t)(5 * 64 * SA + 4 * 4096) * sizeof(float);
    cudaFuncSetAttribute(block_kernel,
                         cudaFuncAttributeMaxDynamicSharedMemorySize, (int)smem);
    block_kernel<<<4096, 256, smem>>>(x, Wq, Wk, Wv, Wo, bo, W1, b1, W2, b2,
                                      g1, be1, g2, be2, out);
}

// round 2
// speedup vs baseline: 1.0005x; 1.0005x over previous
#include <cuda_runtime.h>

// Transformer block, fused, fp32, f32x2-packed FMA path.
// B=4096 batches, T=64 tokens, C=64 embd, H=8 heads, D=8 head_size, FF=256.
// One CTA per batch element, 256 threads (8 warps).

#define Tn 64
#define Cn 64
#define Hn 8
#define SA 68          // padded row stride for activation buffers (floats)
#define EPSV 1e-5f
#define SCALEV 0.125f  // 64^-0.5

typedef unsigned long long ull;

__device__ __forceinline__ ull pack2(float a, float b) {
    ull r;
    asm("mov.b64 %0, {%1, %2};" : "=l"(r) : "f"(a), "f"(b));
    return r;
}
__device__ __forceinline__ void unpack2(ull v, float& a, float& b) {
    asm("mov.b64 {%0, %1}, %2;" : "=f"(a), "=f"(b) : "l"(v));
}
__device__ __forceinline__ ull fma2(ull a, ull b, ull c) {
    ull d;
    asm("fma.rn.f32x2 %0, %1, %2, %3;" : "=l"(d) : "l"(a), "l"(b), "l"(c));
    return d;
}
__device__ __forceinline__ ull mul2(ull a, ull b) {
    ull d;
    asm("mul.rn.f32x2 %0, %1, %2;" : "=l"(d) : "l"(a), "l"(b));
    return d;
}

// C[4x4] += A[4x64] * W[64x4]  (A stride SA, W stride 64)
// acc[i][0] = cols (c0, c0+1), acc[i][1] = cols (c0+2, c0+3), rows r0..r0+3
__device__ __forceinline__ void gemm_tile(const float* __restrict__ A,
                                          const float* __restrict__ W,
                                          ull acc[4][2], int r0, int c0) {
    #pragma unroll 4
    for (int k0 = 0; k0 < 64; k0 += 4) {
        float4 a0 = *(const float4*)&A[(r0 + 0) * SA + k0];
        float4 a1 = *(const float4*)&A[(r0 + 1) * SA + k0];
        float4 a2 = *(const float4*)&A[(r0 + 2) * SA + k0];
        float4 a3 = *(const float4*)&A[(r0 + 3) * SA + k0];
        #pragma unroll
        for (int j = 0; j < 4; j++) {
            float4 w = *(const float4*)&W[(k0 + j) * 64 + c0];
            ull wlo = pack2(w.x, w.y);
            ull whi = pack2(w.z, w.w);
            float e0 = (j == 0) ? a0.x : (j == 1) ? a0.y : (j == 2) ? a0.z : a0.w;
            float e1 = (j == 0) ? a1.x : (j == 1) ? a1.y : (j == 2) ? a1.z : a1.w;
            float e2 = (j == 0) ? a2.x : (j == 1) ? a2.y : (j == 2) ? a2.z : a2.w;
            float e3 = (j == 0) ? a3.x : (j == 1) ? a3.y : (j == 2) ? a3.z : a3.w;
            ull p0 = pack2(e0, e0), p1 = pack2(e1, e1);
            ull p2 = pack2(e2, e2), p3 = pack2(e3, e3);
            acc[0][0] = fma2(p0, wlo, acc[0][0]);
            acc[0][1] = fma2(p0, whi, acc[0][1]);
            acc[1][0] = fma2(p1, wlo, acc[1][0]);
            acc[1][1] = fma2(p1, whi, acc[1][1]);
            acc[2][0] = fma2(p2, wlo, acc[2][0]);
            acc[2][1] = fma2(p2, whi, acc[2][1]);
            acc[3][0] = fma2(p3, wlo, acc[3][0]);
            acc[3][1] = fma2(p3, whi, acc[3][1]);
        }
    }
}

__global__ void __launch_bounds__(256, 1)
block_kernel(const float* __restrict__ x,
             const float* __restrict__ Wq, const float* __restrict__ Wk,
             const float* __restrict__ Wv, const float* __restrict__ Wo,
             const float* __restrict__ bo,
             const float* __restrict__ W1, const float* __restrict__ b1,
             const float* __restrict__ W2, const float* __restrict__ b2,
             const float* __restrict__ g1, const float* __restrict__ be1,
             const float* __restrict__ g2, const float* __restrict__ be2,
             float* __restrict__ out) {
    extern __shared__ float sm[];
    float* xs = sm;                 // 64*SA : residual / x1
    float* hs = xs + 64 * SA;       // 64*SA : LN out / attn out
    float* qs = hs + 64 * SA;       // 64*SA
    float* ks = qs + 64 * SA;       // 64*SA
    float* vs = ks + 64 * SA;       // 64*SA
    float* wb = vs + 64 * SA;       // 4*4096 : Wq,Wk,Wv,Wo -> later W1c,W2c
    float* fs = qs;                 // alias: relu activations (FF phase)

    const int tid = threadIdx.x;
    const int b = blockIdx.x;
    const float* xg = x + (size_t)b * (Tn * Cn);
    float* og = out + (size_t)b * (Tn * Cn);

    // ---- Phase 0: stage attention weights, load x, LN1 -> hs ----
    {
        const float* srcs[4] = {Wq, Wk, Wv, Wo};
        #pragma unroll
        for (int m = 0; m < 4; m++) {
            const float4* s4 = (const float4*)srcs[m];
            float4* d4 = (float4*)(wb + m * 4096);
            #pragma unroll
            for (int p = tid; p < 1024; p += 256) d4[p] = s4[p];
        }
    }
    {
        const int t = tid >> 2, g = tid & 3;
        float4 xv[4];
        float s = 0.f, ss = 0.f;
        #pragma unroll
        for (int i = 0; i < 4; i++) {
            xv[i] = *(const float4*)&xg[t * 64 + g * 16 + i * 4];
            s += xv[i].x + xv[i].y + xv[i].z + xv[i].w;
            ss += xv[i].x * xv[i].x + xv[i].y * xv[i].y +
                  xv[i].z * xv[i].z + xv[i].w * xv[i].w;
        }
        s  += __shfl_xor_sync(0xffffffffu, s, 1);
        s  += __shfl_xor_sync(0xffffffffu, s, 2);
        ss += __shfl_xor_sync(0xffffffffu, ss, 1);
        ss += __shfl_xor_sync(0xffffffffu, ss, 2);
        float mu = s * (1.0f / 64.0f);
        float var = ss * (1.0f / 64.0f) - mu * mu;
        float rstd = rsqrtf(var + EPSV);
        #pragma unroll
        for (int i = 0; i < 4; i++) {
            int c = g * 16 + i * 4;
            float4 gv = *(const float4*)&g1[c];
            float4 bv = *(const float4*)&be1[c];
            float4 hv;
            hv.x = (xv[i].x - mu) * rstd * gv.x + bv.x;
            hv.y = (xv[i].y - mu) * rstd * gv.y + bv.y;
            hv.z = (xv[i].z - mu) * rstd * gv.z + bv.z;
            hv.w = (xv[i].w - mu) * rstd * gv.w + bv.w;
            *(float4*)&xs[t * SA + c] = xv[i];
            *(float4*)&hs[t * SA + c] = hv;
        }
    }
    __syncthreads();

    const int rg = tid >> 4, cg = tid & 15;
    const int r0 = rg * 4, c0 = cg * 4;

    // ---- Phase 1: q,k,v = hs @ Wq/k/v   (q pre-scaled by 0.125) ----
    {
        float* outs[3] = {qs, ks, vs};
        #pragma unroll
        for (int m = 0; m < 3; m++) {
            ull acc[4][2] = {{0, 0}, {0, 0}, {0, 0}, {0, 0}};
            gemm_tile(hs, wb + m * 4096, acc, r0, c0);
            const float scale = (m == 0) ? SCALEV : 1.0f;
            #pragma unroll
            for (int i = 0; i < 4; i++) {
                float v0, v1, v2, v3;
                unpack2(acc[i][0], v0, v1);
                unpack2(acc[i][1], v2, v3);
                float4 o = {v0 * scale, v1 * scale, v2 * scale, v3 * scale};
                *(float4*)&outs[m][(r0 + i) * SA + c0] = o;
            }
        }
    }
    __syncthreads();

    // ---- Phase 2: causal attention (warp = head, lane rows {l, 63-l}) ----
    {
        const int wrp = tid >> 5, l = tid & 31;
        const int hoff = wrp * 8;
        #pragma unroll
        for (int rr = 0; rr < 2; rr++) {
            const int t = (rr == 0) ? l : (63 - l);
            float4 q0 = *(const float4*)&qs[t * SA + hoff];
            float4 q1 = *(const float4*)&qs[t * SA + hoff + 4];
            ull qp0 = pack2(q0.x, q0.y), qp1 = pack2(q0.z, q0.w);
            ull qp2 = pack2(q1.x, q1.y), qp3 = pack2(q1.z, q1.w);
            ull o0 = 0, o1 = 0, o2 = 0, o3 = 0;
            float sum = 0.f;
            for (int s = 0; s <= t; s++) {
                float4 k0v = *(const float4*)&ks[s * SA + hoff];
                float4 k1v = *(const float4*)&ks[s * SA + hoff + 4];
                ull sc = fma2(qp0, pack2(k0v.x, k0v.y), 0ull);
                sc = fma2(qp1, pack2(k0v.z, k0v.w), sc);
                sc = fma2(qp2, pack2(k1v.x, k1v.y), sc);
                sc = fma2(qp3, pack2(k1v.z, k1v.w), sc);
                float sa, sb;
                unpack2(sc, sa, sb);
                float e = __expf(sa + sb);   // scores tiny: max-sub not needed
                sum += e;
                ull ep = pack2(e, e);
                float4 v0v = *(const float4*)&vs[s * SA + hoff];
                float4 v1v = *(const float4*)&vs[s * SA + hoff + 4];
                o0 = fma2(ep, pack2(v0v.x, v0v.y), o0);
                o1 = fma2(ep, pack2(v0v.z, v0v.w), o1);
                o2 = fma2(ep, pack2(v1v.x, v1v.y), o2);
                o3 = fma2(ep, pack2(v1v.z, v1v.w), o3);
            }
            float inv = 1.0f / sum;
            ull ip = pack2(inv, inv);
            *(ull*)&hs[t * SA + hoff + 0] = mul2(o0, ip);
            *(ull*)&hs[t * SA + hoff + 2] = mul2(o1, ip);
            *(ull*)&hs[t * SA + hoff + 4] = mul2(o2, ip);
            *(ull*)&hs[t * SA + hoff + 6] = mul2(o3, ip);
        }
    }
    __syncthreads();

    // ---- Phase 3: x1 = x + attn @ Wo + bo   (in-place into xs) ----
    {
        ull acc[4][2] = {{0, 0}, {0, 0}, {0, 0}, {0, 0}};
        gemm_tile(hs, wb + 3 * 4096, acc, r0, c0);
        float4 bov = *(const float4*)&bo[c0];
        #pragma unroll
        for (int i = 0; i < 4; i++) {
            float v0, v1, v2, v3;
            unpack2(acc[i][0], v0, v1);
            unpack2(acc[i][1], v2, v3);
            float4 xv = *(const float4*)&xs[(r0 + i) * SA + c0];
            xv.x += v0 + bov.x;
            xv.y += v1 + bov.y;
            xv.z += v2 + bov.z;
            xv.w += v3 + bov.w;
            *(float4*)&xs[(r0 + i) * SA + c0] = xv;
        }
    }
    __syncthreads();

    // ---- Phase 4: LN2(xs) -> hs ----
    {
        const int t = tid >> 2, g = tid & 3;
        float4 xv[4];
        float s = 0.f, ss = 0.f;
        #pragma unroll
        for (int i = 0; i < 4; i++) {
            xv[i] = *(const float4*)&xs[t * SA + g * 16 + i * 4];
            s += xv[i].x + xv[i].y + xv[i].z + xv[i].w;
            ss += xv[i].x * xv[i].x + xv[i].y * xv[i].y +
                  xv[i].z * xv[i].z + xv[i].w * xv[i].w;
        }
        s  += __shfl_xor_sync(0xffffffffu, s, 1);
        s  += __shfl_xor_sync(0xffffffffu, s, 2);
        ss += __shfl_xor_sync(0xffffffffu, ss, 1);
        ss += __shfl_xor_sync(0xffffffffu, ss, 2);
        float mu = s * (1.0f / 64.0f);
        float var = ss * (1.0f / 64.0f) - mu * mu;
        float rstd = rsqrtf(var + EPSV);
        #pragma unroll
        for (int i = 0; i < 4; i++) {
            int c = g * 16 + i * 4;
            float4 gv = *(const float4*)&g2[c];
            float4 bv = *(const float4*)&be2[c];
            float4 hv;
            hv.x = (xv[i].x - mu) * rstd * gv.x + bv.x;
            hv.y = (xv[i].y - mu) * rstd * gv.y + bv.y;
            hv.z = (xv[i].z - mu) * rstd * gv.z + bv.z;
            hv.w = (xv[i].w - mu) * rstd * gv.w + bv.w;
            *(float4*)&hs[t * SA + c] = hv;
        }
    }
    __syncthreads();

    // ---- Phase 5: FFN in 4 hidden chunks of 64; FF2 acc in registers ----
    ull accf[4][2] = {{0, 0}, {0, 0}, {0, 0}, {0, 0}};
    for (int cch = 0; cch < 4; cch++) {
        // stage W1 chunk (cols cch*64..) and W2 chunk (rows cch*64..)
        #pragma unroll
        for (int p = tid; p < 1024; p += 256) {
            int k = p >> 4, j4 = p & 15;
            *(float4*)&wb[k * 64 + j4 * 4] =
                *(const float4*)&W1[k * 256 + cch * 64 + j4 * 4];
        }
        {
            const float4* s4 = (const float4*)(W2 + cch * 4096);
            float4* d4 = (float4*)(wb + 4096);
            #pragma unroll
            for (int p = tid; p < 1024; p += 256) d4[p] = s4[p];
        }
        __syncthreads();

        // a1 = relu(hs @ W1c + b1c) -> fs
        {
            ull a1[4][2] = {{0, 0}, {0, 0}, {0, 0}, {0, 0}};
            gemm_tile(hs, wb, a1, r0, c0);
            float4 b1v = *(const float4*)&b1[cch * 64 + c0];
            #pragma unroll
            for (int i = 0; i < 4; i++) {
                float v0, v1, v2, v3;
                unpack2(a1[i][0], v0, v1);
                unpack2(a1[i][1], v2, v3);
                float4 o;
                o.x = fmaxf(v0 + b1v.x, 0.f);
                o.y = fmaxf(v1 + b1v.y, 0.f);
                o.z = fmaxf(v2 + b1v.z, 0.f);
                o.w = fmaxf(v3 + b1v.w, 0.f);
                *(float4*)&fs[(r0 + i) * SA + c0] = o;
            }
        }
        __syncthreads();

        // accf += fs @ W2c
        gemm_tile(fs, wb + 4096, accf, r0, c0);
        __syncthreads();  // protect wb before next chunk's staging
    }

    // ---- Phase 6: out = x1 + ff + b2 ----
    {
        float4 b2v = *(const float4*)&b2[c0];
        #pragma unroll
        for (int i = 0; i < 4; i++) {
            float v0, v1, v2, v3;
            unpack2(accf[i][0], v0, v1);
            unpack2(accf[i][1], v2, v3);
            float4 xv = *(const float4*)&xs[(r0 + i) * SA + c0];
            float4 o;
            o.x = xv.x + v0 + b2v.x;
            o.y = xv.y + v1 + b2v.y;
            o.z = xv.z + v2 + b2v.z;
            o.w = xv.w + v3 + b2v.w;
            *(float4*)&og[(r0 + i) * 64 + c0] = o;
        }
    }
}

extern "C" void kernel_launch(void* const* d_in, const int* in_sizes, int n_in,
                              void* d_out, int out_size) {
    (void)in_sizes; (void)n_in; (void)out_size;
    const float* x   = (const float*)d_in[0];
    const float* Wq  = (const float*)d_in[1];
    const float* Wk  = (const float*)d_in[2];
    const float* Wv  = (const float*)d_in[3];
    const float* Wo  = (const float*)d_in[4];
    const float* bo  = (const float*)d_in[5];
    const float* W1  = (const float*)d_in[6];
    const float* b1  = (const float*)d_in[7];
    const float* W2  = (const float*)d_in[8];
    const float* b2  = (const float*)d_in[9];
    const float* g1  = (const float*)d_in[10];
    const float* be1 = (const float*)d_in[11];
    const float* g2  = (const float*)d_in[12];
    const float* be2 = (const float*)d_in[13];
    float* out = (float*)d_out;

    const size_t smem = (size_t)(5 * 64 * SA + 4 * 4096) * sizeof(float);
    cudaFuncSetAttribute(block_kernel,
                         cudaFuncAttributeMaxDynamicSharedMemorySize, (int)smem);
    block_kernel<<<4096, 256, smem>>>(x, Wq, Wk, Wv, Wo, bo, W1, b1, W2, b2,
                                      g1, be1, g2, be2, out);
}

// round 3
// speedup vs baseline: 1.0014x; 1.0009x over previous
#include <cuda_runtime.h>

// Transformer block, fused, fp32, f32x2-packed FMA path.
// B=4096 batches, T=64 tokens, C=64 embd, H=8 heads, D=8 head_size, FF=256.
// One CTA per batch element, 256 threads (8 warps).

#define Tn 64
#define Cn 64
#define Hn 8
#define SA 68          // padded row stride for activation buffers (floats)
#define EPSV 1e-5f
#define SCALEV 0.125f  // 64^-0.5

typedef unsigned long long ull;

__device__ __forceinline__ ull pack2(float a, float b) {
    ull r;
    asm("mov.b64 %0, {%1, %2};" : "=l"(r) : "f"(a), "f"(b));
    return r;
}
__device__ __forceinline__ void unpack2(ull v, float& a, float& b) {
    asm("mov.b64 {%0, %1}, %2;" : "=f"(a), "=f"(b) : "l"(v));
}
__device__ __forceinline__ ull fma2(ull a, ull b, ull c) {
    ull d;
    asm("fma.rn.f32x2 %0, %1, %2, %3;" : "=l"(d) : "l"(a), "l"(b), "l"(c));
    return d;
}
__device__ __forceinline__ ull mul2(ull a, ull b) {
    ull d;
    asm("mul.rn.f32x2 %0, %1, %2;" : "=l"(d) : "l"(a), "l"(b));
    return d;
}

// C[4x4] += A[4x64] * W[64x4]  (A stride SA, W stride 64)
// acc[i][0] = cols (c0, c0+1), acc[i][1] = cols (c0+2, c0+3), rows r0..r0+3
__device__ __forceinline__ void gemm_tile(const float* __restrict__ A,
                                          const float* __restrict__ W,
                                          ull acc[4][2], int r0, int c0) {
    #pragma unroll 4
    for (int k0 = 0; k0 < 64; k0 += 4) {
        float4 a0 = *(const float4*)&A[(r0 + 0) * SA + k0];
        float4 a1 = *(const float4*)&A[(r0 + 1) * SA + k0];
        float4 a2 = *(const float4*)&A[(r0 + 2) * SA + k0];
        float4 a3 = *(const float4*)&A[(r0 + 3) * SA + k0];
        #pragma unroll
        for (int j = 0; j < 4; j++) {
            float4 w = *(const float4*)&W[(k0 + j) * 64 + c0];
            ull wlo = pack2(w.x, w.y);
            ull whi = pack2(w.z, w.w);
            float e0 = (j == 0) ? a0.x : (j == 1) ? a0.y : (j == 2) ? a0.z : a0.w;
            float e1 = (j == 0) ? a1.x : (j == 1) ? a1.y : (j == 2) ? a1.z : a1.w;
            float e2 = (j == 0) ? a2.x : (j == 1) ? a2.y : (j == 2) ? a2.z : a2.w;
            float e3 = (j == 0) ? a3.x : (j == 1) ? a3.y : (j == 2) ? a3.z : a3.w;
            ull p0 = pack2(e0, e0), p1 = pack2(e1, e1);
            ull p2 = pack2(e2, e2), p3 = pack2(e3, e3);
            acc[0][0] = fma2(p0, wlo, acc[0][0]);
            acc[0][1] = fma2(p0, whi, acc[0][1]);
            acc[1][0] = fma2(p1, wlo, acc[1][0]);
            acc[1][1] = fma2(p1, whi, acc[1][1]);
            acc[2][0] = fma2(p2, wlo, acc[2][0]);
            acc[2][1] = fma2(p2, whi, acc[2][1]);
            acc[3][0] = fma2(p3, wlo, acc[3][0]);
            acc[3][1] = fma2(p3, whi, acc[3][1]);
        }
    }
}

__global__ void __launch_bounds__(256, 1)
block_kernel(const float* __restrict__ x,
             const float* __restrict__ Wq, const float* __restrict__ Wk,
             const float* __restrict__ Wv, const float* __restrict__ Wo,
             const float* __restrict__ bo,
             const float* __restrict__ W1, const float* __restrict__ b1,
             const float* __restrict__ W2, const float* __restrict__ b2,
             const float* __restrict__ g1, const float* __restrict__ be1,
             const float* __restrict__ g2, const float* __restrict__ be2,
             float* __restrict__ out) {
    extern __shared__ float sm[];
    float* xs = sm;                 // 64*SA : residual / x1
    float* hs = xs + 64 * SA;       // 64*SA : LN out / attn out
    float* qs = hs + 64 * SA;       // 64*SA
    float* ks = qs + 64 * SA;       // 64*SA
    float* vs = ks + 64 * SA;       // 64*SA
    float* wb = vs + 64 * SA;       // 4*4096 : Wq,Wk,Wv,Wo -> later W1c,W2c
    float* fs = qs;                 // alias: relu activations (FF phase)

    const int tid = threadIdx.x;
    const int b = blockIdx.x;
    const float* xg = x + (size_t)b * (Tn * Cn);
    float* og = out + (size_t)b * (Tn * Cn);

    // ---- Phase 0: stage attention weights, load x, LN1 -> hs ----
    {
        const float* srcs[4] = {Wq, Wk, Wv, Wo};
        #pragma unroll
        for (int m = 0; m < 4; m++) {
            const float4* s4 = (const float4*)srcs[m];
            float4* d4 = (float4*)(wb + m * 4096);
            #pragma unroll
            for (int p = tid; p < 1024; p += 256) d4[p] = s4[p];
        }
    }
    {
        const int t = tid >> 2, g = tid & 3;
        float4 xv[4];
        float s = 0.f, ss = 0.f;
        #pragma unroll
        for (int i = 0; i < 4; i++) {
            xv[i] = *(const float4*)&xg[t * 64 + g * 16 + i * 4];
            s += xv[i].x + xv[i].y + xv[i].z + xv[i].w;
            ss += xv[i].x * xv[i].x + xv[i].y * xv[i].y +
                  xv[i].z * xv[i].z + xv[i].w * xv[i].w;
        }
        s  += __shfl_xor_sync(0xffffffffu, s, 1);
        s  += __shfl_xor_sync(0xffffffffu, s, 2);
        ss += __shfl_xor_sync(0xffffffffu, ss, 1);
        ss += __shfl_xor_sync(0xffffffffu, ss, 2);
        float mu = s * (1.0f / 64.0f);
        float var = ss * (1.0f / 64.0f) - mu * mu;
        float rstd = rsqrtf(var + EPSV);
        #pragma unroll
        for (int i = 0; i < 4; i++) {
            int c = g * 16 + i * 4;
            float4 gv = *(const float4*)&g1[c];
            float4 bv = *(const float4*)&be1[c];
            float4 hv;
            hv.x = (xv[i].x - mu) * rstd * gv.x + bv.x;
            hv.y = (xv[i].y - mu) * rstd * gv.y + bv.y;
            hv.z = (xv[i].z - mu) * rstd * gv.z + bv.z;
            hv.w = (xv[i].w - mu) * rstd * gv.w + bv.w;
            *(float4*)&xs[t * SA + c] = xv[i];
            *(float4*)&hs[t * SA + c] = hv;
        }
    }
    __syncthreads();

    const int rg = tid >> 4, cg = tid & 15;
    const int r0 = rg * 4, c0 = cg * 4;

    // ---- Phase 1: q,k,v = hs @ Wq/k/v   (q pre-scaled by 0.125) ----
    {
        float* outs[3] = {qs, ks, vs};
        #pragma unroll
        for (int m = 0; m < 3; m++) {
            ull acc[4][2] = {{0, 0}, {0, 0}, {0, 0}, {0, 0}};
            gemm_tile(hs, wb + m * 4096, acc, r0, c0);
            const float scale = (m == 0) ? SCALEV : 1.0f;
            #pragma unroll
            for (int i = 0; i < 4; i++) {
                float v0, v1, v2, v3;
                unpack2(acc[i][0], v0, v1);
                unpack2(acc[i][1], v2, v3);
                float4 o = {v0 * scale, v1 * scale, v2 * scale, v3 * scale};
                *(float4*)&outs[m][(r0 + i) * SA + c0] = o;
            }
        }
    }
    __syncthreads();

    // ---- Phase 2: causal attention (warp = head, lane rows {l, 63-l}) ----
    {
        const int wrp = tid >> 5, l = tid & 31;
        const int hoff = wrp * 8;
        #pragma unroll
        for (int rr = 0; rr < 2; rr++) {
            const int t = (rr == 0) ? l : (63 - l);
            float4 q0 = *(const float4*)&qs[t * SA + hoff];
            float4 q1 = *(const float4*)&qs[t * SA + hoff + 4];
            ull qp0 = pack2(q0.x, q0.y), qp1 = pack2(q0.z, q0.w);
            ull qp2 = pack2(q1.x, q1.y), qp3 = pack2(q1.z, q1.w);
            ull o0 = 0, o1 = 0, o2 = 0, o3 = 0;
            float sum = 0.f;
            for (int s = 0; s <= t; s++) {
                float4 k0v = *(const float4*)&ks[s * SA + hoff];
                float4 k1v = *(const float4*)&ks[s * SA + hoff + 4];
                ull sc = fma2(qp0, pack2(k0v.x, k0v.y), 0ull);
                sc = fma2(qp1, pack2(k0v.z, k0v.w), sc);
                sc = fma2(qp2, pack2(k1v.x, k1v.y), sc);
                sc = fma2(qp3, pack2(k1v.z, k1v.w), sc);
                float sa, sb;
                unpack2(sc, sa, sb);
                float e = __expf(sa + sb);   // scores tiny: max-sub not needed
                sum += e;
                ull ep = pack2(e, e);
                float4 v0v = *(const float4*)&vs[s * SA + hoff];
                float4 v1v = *(const float4*)&vs[s * SA + hoff + 4];
                o0 = fma2(ep, pack2(v0v.x, v0v.y), o0);
                o1 = fma2(ep, pack2(v0v.z, v0v.w), o1);
                o2 = fma2(ep, pack2(v1v.x, v1v.y), o2);
                o3 = fma2(ep, pack2(v1v.z, v1v.w), o3);
            }
            float inv = 1.0f / sum;
            ull ip = pack2(inv, inv);
            *(ull*)&hs[t * SA + hoff + 0] = mul2(o0, ip);
            *(ull*)&hs[t * SA + hoff + 2] = mul2(o1, ip);
            *(ull*)&hs[t * SA + hoff + 4] = mul2(o2, ip);
            *(ull*)&hs[t * SA + hoff + 6] = mul2(o3, ip);
        }
    }
    __syncthreads();

    // ---- Phase 3: x1 = x + attn @ Wo + bo   (in-place into xs) ----
    {
        ull acc[4][2] = {{0, 0}, {0, 0}, {0, 0}, {0, 0}};
        gemm_tile(hs, wb + 3 * 4096, acc, r0, c0);
        float4 bov = *(const float4*)&bo[c0];
        #pragma unroll
        for (int i = 0; i < 4; i++) {
            float v0, v1, v2, v3;
            unpack2(acc[i][0], v0, v1);
            unpack2(acc[i][1], v2, v3);
            float4 xv = *(const float4*)&xs[(r0 + i) * SA + c0];
            xv.x += v0 + bov.x;
            xv.y += v1 + bov.y;
            xv.z += v2 + bov.z;
            xv.w += v3 + bov.w;
            *(float4*)&xs[(r0 + i) * SA + c0] = xv;
        }
    }
    __syncthreads();

    // ---- Phase 4: LN2(xs) -> hs ----
    {
        const int t = tid >> 2, g = tid & 3;
        float4 xv[4];
        float s = 0.f, ss = 0.f;
        #pragma unroll
        for (int i = 0; i < 4; i++) {
            xv[i] = *(const float4*)&xs[t * SA + g * 16 + i * 4];
            s += xv[i].x + xv[i].y + xv[i].z + xv[i].w;
            ss += xv[i].x * xv[i].x + xv[i].y * xv[i].y +
                  xv[i].z * xv[i].z + xv[i].w * xv[i].w;
        }
        s  += __shfl_xor_sync(0xffffffffu, s, 1);
        s  += __shfl_xor_sync(0xffffffffu, s, 2);
        ss += __shfl_xor_sync(0xffffffffu, ss, 1);
        ss += __shfl_xor_sync(0xffffffffu, ss, 2);
        float mu = s * (1.0f / 64.0f);
        float var = ss * (1.0f / 64.0f) - mu * mu;
        float rstd = rsqrtf(var + EPSV);
        #pragma unroll
        for (int i = 0; i < 4; i++) {
            int c = g * 16 + i * 4;
            float4 gv = *(const float4*)&g2[c];
            float4 bv = *(const float4*)&be2[c];
            float4 hv;
            hv.x = (xv[i].x - mu) * rstd * gv.x + bv.x;
            hv.y = (xv[i].y - mu) * rstd * gv.y + bv.y;
            hv.z = (xv[i].z - mu) * rstd * gv.z + bv.z;
            hv.w = (xv[i].w - mu) * rstd * gv.w + bv.w;
            *(float4*)&hs[t * SA + c] = hv;
        }
    }
    __syncthreads();

    // ---- Phase 5: FFN in 4 hidden chunks of 64; FF2 acc in registers ----
    ull accf[4][2] = {{0, 0}, {0, 0}, {0, 0}, {0, 0}};
    for (int cch = 0; cch < 4; cch++) {
        // stage W1 chunk (cols cch*64..) and W2 chunk (rows cch*64..)
        #pragma unroll
        for (int p = tid; p < 1024; p += 256) {
            int k = p >> 4, j4 = p & 15;
            *(float4*)&wb[k * 64 + j4 * 4] =
                *(const float4*)&W1[k * 256 + cch * 64 + j4 * 4];
        }
        {
            const float4* s4 = (const float4*)(W2 + cch * 4096);
            float4* d4 = (float4*)(wb + 4096);
            #pragma unroll
            for (int p = tid; p < 1024; p += 256) d4[p] = s4[p];
        }
        __syncthreads();

        // a1 = relu(hs @ W1c + b1c) -> fs
        {
            ull a1[4][2] = {{0, 0}, {0, 0}, {0, 0}, {0, 0}};
            gemm_tile(hs, wb, a1, r0, c0);
            float4 b1v = *(const float4*)&b1[cch * 64 + c0];
            #pragma unroll
            for (int i = 0; i < 4; i++) {
                float v0, v1, v2, v3;
                unpack2(a1[i][0], v0, v1);
                unpack2(a1[i][1], v2, v3);
                float4 o;
                o.x = fmaxf(v0 + b1v.x, 0.f);
                o.y = fmaxf(v1 + b1v.y, 0.f);
                o.z = fmaxf(v2 + b1v.z, 0.f);
                o.w = fmaxf(v3 + b1v.w, 0.f);
                *(float4*)&fs[(r0 + i) * SA + c0] = o;
            }
        }
        __syncthreads();

        // accf += fs @ W2c
        gemm_tile(fs, wb + 4096, accf, r0, c0);
        __syncthreads();  // protect wb before next chunk's staging
    }

    // ---- Phase 6: out = x1 + ff + b2 ----
    {
        float4 b2v = *(const float4*)&b2[c0];
        #pragma unroll
        for (int i = 0; i < 4; i++) {
            float v0, v1, v2, v3;
            unpack2(accf[i][0], v0, v1);
            unpack2(accf[i][1], v2, v3);
            float4 xv = *(const float4*)&xs[(r0 + i) * SA + c0];
            float4 o;
            o.x = xv.x + v0 + b2v.x;
            o.y = xv.y + v1 + b2v.y;
            o.z = xv.z + v2 + b2v.z;
            o.w = xv.w + v3 + b2v.w;
            *(float4*)&og[(r0 + i) * 64 + c0] = o;
        }
    }
}

extern "C" void kernel_launch(void* const* d_in, const int* in_sizes, int n_in,
                              void* d_out, int out_size) {
    (void)in_sizes; (void)n_in; (void)out_size;
    const float* x   = (const float*)d_in[0];
    const float* Wq  = (const float*)d_in[1];
    const float* Wk  = (const float*)d_in[2];
    const float* Wv  = (const float*)d_in[3];
    const float* Wo  = (const float*)d_in[4];
    const float* bo  = (const float*)d_in[5];
    const float* W1  = (const float*)d_in[6];
    const float* b1  = (const float*)d_in[7];
    const float* W2  = (const float*)d_in[8];
    const float* b2  = (const float*)d_in[9];
    const float* g1  = (const float*)d_in[10];
    const float* be1 = (const float*)d_in[11];
    const float* g2  = (const float*)d_in[12];
    const float* be2 = (const float*)d_in[13];
    float* out = (float*)d_out;

    const size_t smem = (size_t)(5 * 64 * SA + 4 * 4096) * sizeof(float);
    cudaFuncSetAttribute(block_kernel,
                         cudaFuncAttributeMaxDynamicSharedMemorySize, (int)smem);
    block_kernel<<<4096, 256, smem>>>(x, Wq, Wk, Wv, Wo, bo, W1, b1, W2, b2,
                                      g1, be1, g2, be2, out);
}